// round 3
// baseline (speedup 1.0000x reference)
#include <cuda_runtime.h>
#include <cuda_bf16.h>

#define HDIM   128
#define HHALF  64
#define MTILE  128
#define K1_THREADS 256

// -------- scratch (no allocations allowed) --------
__device__ float g_s[1048576];             // per-row scores s[N]
__device__ float g_attn_fallback[1048576]; // only used if out layout != pooled|attn
__device__ int   g_offs[65544];            // segment offsets [G+1]

// packed fp32x2 FMA (Blackwell). d = a*b + c elementwise on 2 floats.
static __device__ __forceinline__ float2 ffma2(float2 a, float2 b, float2 c) {
    float2 d;
    asm("fma.rn.f32x2 %0, %1, %2, %3;"
        : "=l"(reinterpret_cast<unsigned long long&>(d))
        : "l"(reinterpret_cast<unsigned long long&>(a)),
          "l"(reinterpret_cast<unsigned long long&>(b)),
          "l"(reinterpret_cast<unsigned long long&>(c)));
    return d;
}

// ---------------------------------------------------------------------------
// Kernel 0: segment offsets via binary search on sorted batch.
// g_offs[g] = lower_bound(batch, g);  g_offs[G] = N.
// ---------------------------------------------------------------------------
__global__ void seg_offsets_kernel(const int* __restrict__ batch, int n, int g_count)
{
    int g = blockIdx.x * blockDim.x + threadIdx.x;
    if (g > g_count) return;
    int lo = 0, hi = n;
    while (lo < hi) {
        int mid = (lo + hi) >> 1;
        if (batch[mid] < g) lo = mid + 1; else hi = mid;
    }
    g_offs[g] = lo;
}

// ---------------------------------------------------------------------------
// Kernel 1: s = tanh(x @ W1 + b1) @ W2 + b2   (fused GEMM, fp32 via f32x2)
// Block: 256 threads, 128 rows x 64 cols tile, K=128 fully staged in smem.
// Thread (tx=tid&15, ty=tid>>4): rows 8*ty..+7, cols {tx, tx+16, tx+32, tx+48}.
// f32x2 packs consecutive K pairs -> no operand packing movs.
// ---------------------------------------------------------------------------
__global__ __launch_bounds__(K1_THREADS, 2)
void mlp_score_kernel(const float* __restrict__ x,
                      const float* __restrict__ W1,
                      const float* __restrict__ b1,
                      const float* __restrict__ W2,
                      const float* __restrict__ b2,
                      int n)
{
    extern __shared__ float smem[];
    float*  xs  = smem;                               // [128][132] padded rows
    float2* w1p = (float2*)(smem + MTILE * 132);      // [64 kpairs][64 cols]
    float*  b1s = (float*)(w1p + 64 * 64);            // [64]
    float*  w2s = b1s + HHALF;                        // [64]

    const int tid  = threadIdx.x;
    const int row0 = blockIdx.x * MTILE;

    // stage x tile (128 rows x 128 k) as float4, zero-fill OOB rows
    const float4* xv = reinterpret_cast<const float4*>(x);
    #pragma unroll
    for (int i = tid; i < MTILE * 32; i += K1_THREADS) {
        int r  = i >> 5;
        int cg = i & 31;
        float4 v = make_float4(0.f, 0.f, 0.f, 0.f);
        if (row0 + r < n) v = xv[(size_t)(row0 + r) * 32 + cg];
        *reinterpret_cast<float4*>(&xs[r * 132 + cg * 4]) = v;
    }
    // stage W1 as k-pairs: w1p[p][c] = (W1[2p][c], W1[2p+1][c])
    for (int i = tid; i < 64 * 64; i += K1_THREADS) {
        int p = i >> 6;
        int c = i & 63;
        w1p[i] = make_float2(W1[(2 * p) * HHALF + c], W1[(2 * p + 1) * HHALF + c]);
    }
    if (tid < HHALF) { b1s[tid] = b1[tid]; w2s[tid] = W2[tid]; }
    __syncthreads();

    const int tx = tid & 15;
    const int ty = tid >> 4;

    float2 acc[8][4];
    #pragma unroll
    for (int r = 0; r < 8; r++)
        #pragma unroll
        for (int j = 0; j < 4; j++) acc[r][j] = make_float2(0.f, 0.f);

    const float* xrow = &xs[(ty * 8) * 132];

    #pragma unroll 2
    for (int k = 0; k < HDIM; k += 4) {
        const int p = k >> 1;
        float2 blo[4], bhi[4];
        #pragma unroll
        for (int j = 0; j < 4; j++) {
            int c = tx + 16 * j;
            blo[j] = w1p[p * 64 + c];        // W1 at k,   k+1
            bhi[j] = w1p[(p + 1) * 64 + c];  // W1 at k+2, k+3
        }
        #pragma unroll
        for (int r = 0; r < 8; r++) {
            float4 a4  = *reinterpret_cast<const float4*>(&xrow[r * 132 + k]);
            float2 a01 = make_float2(a4.x, a4.y);
            float2 a23 = make_float2(a4.z, a4.w);
            #pragma unroll
            for (int j = 0; j < 4; j++) {
                acc[r][j] = ffma2(a01, blo[j], acc[r][j]);
                acc[r][j] = ffma2(a23, bhi[j], acc[r][j]);
            }
        }
    }

    // epilogue: tanh + dot with W2, reduce over the 16 tx lanes
    const float b2v = __ldg(b2);
    float part[8];
    #pragma unroll
    for (int r = 0; r < 8; r++) part[r] = 0.f;
    #pragma unroll
    for (int j = 0; j < 4; j++) {
        int c = tx + 16 * j;
        float bc = b1s[c], wc = w2s[c];
        #pragma unroll
        for (int r = 0; r < 8; r++) {
            float pre = (acc[r][j].x + acc[r][j].y) + bc;
            part[r] += tanhf(pre) * wc;
        }
    }
    #pragma unroll
    for (int r = 0; r < 8; r++) {
        #pragma unroll
        for (int off = 8; off > 0; off >>= 1)
            part[r] += __shfl_down_sync(0xffffffffu, part[r], off, 16);
    }
    if (tx == 0) {
        #pragma unroll
        for (int r = 0; r < 8; r++) {
            int row = row0 + ty * 8 + r;
            if (row < n) g_s[row] = part[r] + b2v;
        }
    }
}

// ---------------------------------------------------------------------------
// Kernel 2: per-graph softmax over s + weighted pooling of x.
// One block (128 threads) per graph. thread h owns feature column h.
// ---------------------------------------------------------------------------
__global__ __launch_bounds__(128)
void softmax_pool_kernel(const float* __restrict__ x,
                         float* __restrict__ pooled,
                         float* __restrict__ attn,
                         int n)
{
    const int g   = blockIdx.x;
    const int tid = threadIdx.x;
    const int start = g_offs[g];
    const int end   = g_offs[g + 1];
    const int len   = end - start;

    if (len <= 0) { pooled[(size_t)g * HDIM + tid] = 0.f; return; }

    __shared__ float red[4];
    __shared__ float wsh[512];

    // --- segment max ---
    float mx = -3.402823466e38f;
    for (int i = tid; i < len; i += 128)
        mx = fmaxf(mx, g_s[start + i]);
    #pragma unroll
    for (int o = 16; o > 0; o >>= 1)
        mx = fmaxf(mx, __shfl_xor_sync(0xffffffffu, mx, o));
    if ((tid & 31) == 0) red[tid >> 5] = mx;
    __syncthreads();
    mx = fmaxf(fmaxf(red[0], red[1]), fmaxf(red[2], red[3]));
    __syncthreads();

    // --- segment sum of exp ---
    float sm = 0.f;
    for (int i = tid; i < len; i += 128)
        sm += __expf(g_s[start + i] - mx);
    #pragma unroll
    for (int o = 16; o > 0; o >>= 1)
        sm += __shfl_xor_sync(0xffffffffu, sm, o);
    if ((tid & 31) == 0) red[tid >> 5] = sm;
    __syncthreads();
    sm = (red[0] + red[1]) + (red[2] + red[3]);
    const float inv = 1.f / sm;   // denom >= 1 (max term contributes exp(0)=1)

    // --- weights + weighted pooling ---
    float acc0 = 0.f, acc1 = 0.f, acc2 = 0.f, acc3 = 0.f;
    for (int c0 = 0; c0 < len; c0 += 512) {
        int cl = min(512, len - c0);
        __syncthreads();
        for (int i = tid; i < cl; i += 128) {
            float w = __expf(g_s[start + c0 + i] - mx) * inv;
            wsh[i] = w;
            attn[start + c0 + i] = w;
        }
        __syncthreads();
        const float* xb = x + (size_t)(start + c0) * HDIM + tid;
        int j = 0;
        for (; j + 4 <= cl; j += 4) {
            acc0 = fmaf(xb[(size_t)(j + 0) * HDIM], wsh[j + 0], acc0);
            acc1 = fmaf(xb[(size_t)(j + 1) * HDIM], wsh[j + 1], acc1);
            acc2 = fmaf(xb[(size_t)(j + 2) * HDIM], wsh[j + 2], acc2);
            acc3 = fmaf(xb[(size_t)(j + 3) * HDIM], wsh[j + 3], acc3);
        }
        for (; j < cl; j++)
            acc0 = fmaf(xb[(size_t)j * HDIM], wsh[j], acc0);
    }
    pooled[(size_t)g * HDIM + tid] = (acc0 + acc1) + (acc2 + acc3);
}

// ---------------------------------------------------------------------------
// launch
// ---------------------------------------------------------------------------
extern "C" void kernel_launch(void* const* d_in, const int* in_sizes, int n_in,
                              void* d_out, int out_size)
{
    const float* x     = (const float*)d_in[0];
    const int*   batch = (const int*)  d_in[1];
    const float* W1    = (const float*)d_in[2];
    const float* b1    = (const float*)d_in[3];
    const float* W2    = (const float*)d_in[4];
    const float* b2    = (const float*)d_in[5];

    const int N = in_sizes[1];            // batch element count
    float* out = (float*)d_out;

    // output layout: [x_pooled (G*128) | attn_weights (N)]
    long long rem = (long long)out_size - (long long)N;
    int G;
    float* pooled = out;
    float* attn;
    if (rem > 0 && (rem % HDIM) == 0) {
        G = (int)(rem / HDIM);
        attn = out + (size_t)G * HDIM;
    } else {
        G = out_size / HDIM;              // pooled-only output; park attn in scratch
        void* p = nullptr;
        cudaGetSymbolAddress(&p, g_attn_fallback);
        attn = (float*)p;
    }

    // 0) segment offsets
    int tG = G + 1;
    seg_offsets_kernel<<<(tG + 255) / 256, 256>>>(batch, N, G);

    // 1) fused MLP scores
    const int smem_bytes = (MTILE * 132 + 64 * 64 * 2 + HHALF + HHALF) * (int)sizeof(float);
    cudaFuncSetAttribute(mlp_score_kernel,
                         cudaFuncAttributeMaxDynamicSharedMemorySize, smem_bytes);
    int nblocks = (N + MTILE - 1) / MTILE;
    mlp_score_kernel<<<nblocks, K1_THREADS, smem_bytes>>>(x, W1, b1, W2, b2, N);

    // 2) segmented softmax + pooling
    softmax_pool_kernel<<<G, 128>>>(x, pooled, attn, N);
}

// round 4
// speedup vs baseline: 1.4940x; 1.4940x over previous
#include <cuda_runtime.h>
#include <cuda_bf16.h>

#define HDIM   128
#define HHALF  64
#define BSTRIDE 72          // smem word stride for W1 tiles (bank-conflict-free)

// -------- scratch (no device allocations allowed) --------
__device__ float g_s[1048576];             // per-row scores s[N]
__device__ float g_attn_fallback[1048576]; // only if out layout != pooled|attn

// ---------------------------------------------------------------------------
// helpers
// ---------------------------------------------------------------------------
static __device__ __forceinline__ float fast_tanh(float xv) {
    float ax = fabsf(xv);
    float t  = __expf(-2.0f * ax);
    float r  = __fdividef(1.0f - t, 1.0f + t);
    return copysignf(r, xv);
}

static __device__ __forceinline__ void split_bf16(float2 f, unsigned& hi, unsigned& lo) {
    __nv_bfloat162 h = __floats2bfloat162_rn(f.x, f.y);     // .x in low 16 bits
    float2 hf = __bfloat1622float2(h);
    __nv_bfloat162 l = __floats2bfloat162_rn(f.x - hf.x, f.y - hf.y); // exact (Sterbenz)
    hi = *reinterpret_cast<unsigned*>(&h);
    lo = *reinterpret_cast<unsigned*>(&l);
}

static __device__ __forceinline__ void mma_bf16(float* c, const unsigned* a,
                                                unsigned b0, unsigned b1) {
    asm volatile(
        "mma.sync.aligned.m16n8k16.row.col.f32.bf16.bf16.f32 "
        "{%0,%1,%2,%3}, {%4,%5,%6,%7}, {%8,%9}, {%0,%1,%2,%3};\n"
        : "+f"(c[0]), "+f"(c[1]), "+f"(c[2]), "+f"(c[3])
        : "r"(a[0]), "r"(a[1]), "r"(a[2]), "r"(a[3]), "r"(b0), "r"(b1));
}

// ---------------------------------------------------------------------------
// Kernel 1: s = tanh(x @ W1 + b1) @ W2 + b2
// Tensor-core GEMM, bf16 hi/lo 3-pass split (fp32-equivalent precision).
// Block: 256 threads (8 warps), tile 128 rows x 64 cols, K=128.
// Warp w handles rows [row0 + 16w, +16). A fragments loaded straight from
// global (coalesced 32B runs), W1 hi/lo staged in smem (stride-72 padded).
// ---------------------------------------------------------------------------
__global__ __launch_bounds__(256, 2)
void mlp_score_kernel(const float* __restrict__ x,
                      const float* __restrict__ W1,
                      const float* __restrict__ b1,
                      const float* __restrict__ W2,
                      const float* __restrict__ b2,
                      int n)
{
    extern __shared__ unsigned smem_u[];
    unsigned* w1hi = smem_u;                       // [64 kpairs][BSTRIDE]
    unsigned* w1lo = smem_u + 64 * BSTRIDE;
    float*    b1s  = (float*)(smem_u + 2 * 64 * BSTRIDE);
    float*    w2s  = b1s + HHALF;

    const int tid  = threadIdx.x;
    const int warp = tid >> 5;
    const int lane = tid & 31;
    const int g    = lane >> 2;     // groupID 0..7
    const int tig  = lane & 3;      // thread-in-group 0..3
    const int row0 = blockIdx.x * 128 + warp * 16;

    // ---- stage W1 as bf16 hi/lo in smem ----
    for (int i = tid; i < HDIM * HHALF; i += 256) {
        int k = i >> 6, c = i & 63;
        float v = W1[i];
        __nv_bfloat16 hb = __float2bfloat16(v);
        __nv_bfloat16 lb = __float2bfloat16(v - __bfloat162float(hb));
        int widx = (k >> 1) * BSTRIDE + c;
        int half = k & 1;
        ((__nv_bfloat16*)w1hi)[widx * 2 + half] = hb;
        ((__nv_bfloat16*)w1lo)[widx * 2 + half] = lb;
    }
    if (tid < HHALF) { b1s[tid] = b1[tid]; w2s[tid] = W2[tid]; }
    __syncthreads();

    const int  rowA = row0 + g;
    const int  rowB = row0 + g + 8;
    const bool va   = rowA < n;
    const bool vb   = rowB < n;
    const float2* xa = (const float2*)x + (size_t)rowA * 64;   // kpairs of row A
    const float2* xb = (const float2*)x + (size_t)rowB * 64;

    float C[8][4];
    #pragma unroll
    for (int j = 0; j < 8; j++)
        #pragma unroll
        for (int q = 0; q < 4; q++) C[j][q] = 0.f;

    const float2 z2 = make_float2(0.f, 0.f);

    #pragma unroll
    for (int kh = 0; kh < 2; kh++) {
        // load + split A fragments for 4 k16-steps
        unsigned ahi[4][4], alo[4][4];
        #pragma unroll
        for (int ks = 0; ks < 4; ks++) {
            int kp = (kh * 4 + ks) * 8 + tig;   // global kpair index
            float2 f0 = va ? xa[kp]     : z2;   // row g,   k..k+1
            float2 f1 = vb ? xb[kp]     : z2;   // row g+8, k..k+1
            float2 f2 = va ? xa[kp + 4] : z2;   // row g,   k+8..k+9
            float2 f3 = vb ? xb[kp + 4] : z2;   // row g+8, k+8..k+9
            split_bf16(f0, ahi[ks][0], alo[ks][0]);
            split_bf16(f1, ahi[ks][1], alo[ks][1]);
            split_bf16(f2, ahi[ks][2], alo[ks][2]);
            split_bf16(f3, ahi[ks][3], alo[ks][3]);
        }
        // MMAs
        #pragma unroll
        for (int ks = 0; ks < 4; ks++) {
            int kb = (kh * 4 + ks) * 8;
            #pragma unroll
            for (int j = 0; j < 8; j++) {
                int nn = j * 8 + g;
                unsigned bh0 = w1hi[(kb + tig)     * BSTRIDE + nn];
                unsigned bh1 = w1hi[(kb + tig + 4) * BSTRIDE + nn];
                unsigned bl0 = w1lo[(kb + tig)     * BSTRIDE + nn];
                unsigned bl1 = w1lo[(kb + tig + 4) * BSTRIDE + nn];
                mma_bf16(C[j], ahi[ks], bh0, bh1);   // hi*hi
                mma_bf16(C[j], alo[ks], bh0, bh1);   // lo*hi
                mma_bf16(C[j], ahi[ks], bl0, bl1);   // hi*lo
            }
        }
    }

    // ---- epilogue: tanh + dot(W2), reduce across tig lanes ----
    const float b2v = __ldg(b2);
    float p0 = 0.f, p1 = 0.f;
    #pragma unroll
    for (int j = 0; j < 8; j++) {
        int h0 = j * 8 + tig * 2, h1 = h0 + 1;
        float bb0 = b1s[h0], bb1 = b1s[h1];
        float ww0 = w2s[h0], ww1 = w2s[h1];
        p0 += fast_tanh(C[j][0] + bb0) * ww0 + fast_tanh(C[j][1] + bb1) * ww1;
        p1 += fast_tanh(C[j][2] + bb0) * ww0 + fast_tanh(C[j][3] + bb1) * ww1;
    }
    p0 += __shfl_xor_sync(0xffffffffu, p0, 1);
    p0 += __shfl_xor_sync(0xffffffffu, p0, 2);
    p1 += __shfl_xor_sync(0xffffffffu, p1, 1);
    p1 += __shfl_xor_sync(0xffffffffu, p1, 2);
    if (tig == 0) {
        if (va) g_s[rowA] = p0 + b2v;
        if (vb) g_s[rowB] = p1 + b2v;
    }
}

// ---------------------------------------------------------------------------
// Kernel 2: per-graph softmax over s + weighted pooling of x.
// One block (128 threads) per graph; segment bounds via in-block binary
// search on the sorted batch array (L2-resident, amortized to noise).
// ---------------------------------------------------------------------------
__global__ __launch_bounds__(128)
void softmax_pool_kernel(const float* __restrict__ x,
                         const int*   __restrict__ batch,
                         float* __restrict__ pooled,
                         float* __restrict__ attn,
                         int n)
{
    const int gI  = blockIdx.x;
    const int tid = threadIdx.x;

    __shared__ int   se[2];
    __shared__ float red[4];
    __shared__ float wsh[512];

    if (tid < 2) {
        int target = gI + tid;       // lower_bound(batch, target)
        int lo = 0, hi = n;
        while (lo < hi) {
            int mid = (lo + hi) >> 1;
            if (batch[mid] < target) lo = mid + 1; else hi = mid;
        }
        se[tid] = lo;
    }
    __syncthreads();

    const int start = se[0];
    const int len   = se[1] - se[0];

    if (len <= 0) { pooled[(size_t)gI * HDIM + tid] = 0.f; return; }

    // --- segment max ---
    float mx = -3.402823466e38f;
    for (int i = tid; i < len; i += 128)
        mx = fmaxf(mx, g_s[start + i]);
    #pragma unroll
    for (int o = 16; o > 0; o >>= 1)
        mx = fmaxf(mx, __shfl_xor_sync(0xffffffffu, mx, o));
    if ((tid & 31) == 0) red[tid >> 5] = mx;
    __syncthreads();
    mx = fmaxf(fmaxf(red[0], red[1]), fmaxf(red[2], red[3]));
    __syncthreads();

    if (len <= 512) {
        // fast path: cache exp values, one exp evaluation total
        float sm = 0.f;
        for (int i = tid; i < len; i += 128) {
            float e = __expf(g_s[start + i] - mx);
            wsh[i] = e;
            sm += e;
        }
        #pragma unroll
        for (int o = 16; o > 0; o >>= 1)
            sm += __shfl_xor_sync(0xffffffffu, sm, o);
        if ((tid & 31) == 0) red[tid >> 5] = sm;
        __syncthreads();
        sm = (red[0] + red[1]) + (red[2] + red[3]);
        const float inv = 1.f / sm;

        for (int i = tid; i < len; i += 128) {
            float w = wsh[i] * inv;
            wsh[i] = w;
            attn[start + i] = w;
        }
        __syncthreads();

        float acc0 = 0.f, acc1 = 0.f, acc2 = 0.f, acc3 = 0.f;
        const float* xb = x + (size_t)start * HDIM + tid;
        int j = 0;
        for (; j + 4 <= len; j += 4) {
            acc0 = fmaf(xb[(size_t)(j + 0) * HDIM], wsh[j + 0], acc0);
            acc1 = fmaf(xb[(size_t)(j + 1) * HDIM], wsh[j + 1], acc1);
            acc2 = fmaf(xb[(size_t)(j + 2) * HDIM], wsh[j + 2], acc2);
            acc3 = fmaf(xb[(size_t)(j + 3) * HDIM], wsh[j + 3], acc3);
        }
        for (; j < len; j++)
            acc0 = fmaf(xb[(size_t)j * HDIM], wsh[j], acc0);
        pooled[(size_t)gI * HDIM + tid] = (acc0 + acc1) + (acc2 + acc3);
        return;
    }

    // --- general path (len > 512): two-pass exp ---
    float sm = 0.f;
    for (int i = tid; i < len; i += 128)
        sm += __expf(g_s[start + i] - mx);
    #pragma unroll
    for (int o = 16; o > 0; o >>= 1)
        sm += __shfl_xor_sync(0xffffffffu, sm, o);
    if ((tid & 31) == 0) red[tid >> 5] = sm;
    __syncthreads();
    sm = (red[0] + red[1]) + (red[2] + red[3]);
    const float inv = 1.f / sm;

    float acc0 = 0.f, acc1 = 0.f, acc2 = 0.f, acc3 = 0.f;
    for (int c0 = 0; c0 < len; c0 += 512) {
        int cl = min(512, len - c0);
        __syncthreads();
        for (int i = tid; i < cl; i += 128) {
            float w = __expf(g_s[start + c0 + i] - mx) * inv;
            wsh[i] = w;
            attn[start + c0 + i] = w;
        }
        __syncthreads();
        const float* xb = x + (size_t)(start + c0) * HDIM + tid;
        int j = 0;
        for (; j + 4 <= cl; j += 4) {
            acc0 = fmaf(xb[(size_t)(j + 0) * HDIM], wsh[j + 0], acc0);
            acc1 = fmaf(xb[(size_t)(j + 1) * HDIM], wsh[j + 1], acc1);
            acc2 = fmaf(xb[(size_t)(j + 2) * HDIM], wsh[j + 2], acc2);
            acc3 = fmaf(xb[(size_t)(j + 3) * HDIM], wsh[j + 3], acc3);
        }
        for (; j < cl; j++)
            acc0 = fmaf(xb[(size_t)j * HDIM], wsh[j], acc0);
    }
    pooled[(size_t)gI * HDIM + tid] = (acc0 + acc1) + (acc2 + acc3);
}

// ---------------------------------------------------------------------------
// launch
// ---------------------------------------------------------------------------
extern "C" void kernel_launch(void* const* d_in, const int* in_sizes, int n_in,
                              void* d_out, int out_size)
{
    const float* x     = (const float*)d_in[0];
    const int*   batch = (const int*)  d_in[1];
    const float* W1    = (const float*)d_in[2];
    const float* b1    = (const float*)d_in[3];
    const float* W2    = (const float*)d_in[4];
    const float* b2    = (const float*)d_in[5];

    const int N = in_sizes[1];
    float* out = (float*)d_out;

    // output layout: [x_pooled (G*128) | attn_weights (N)]
    long long rem = (long long)out_size - (long long)N;
    int G;
    float* pooled = out;
    float* attn;
    if (rem > 0 && (rem % HDIM) == 0) {
        G = (int)(rem / HDIM);
        attn = out + (size_t)G * HDIM;
    } else {
        G = out_size / HDIM;
        void* p = nullptr;
        cudaGetSymbolAddress(&p, g_attn_fallback);
        attn = (float*)p;
    }

    // 1) fused MLP scores (tensor cores)
    const int smem_bytes = (2 * 64 * BSTRIDE + 2 * HHALF) * (int)sizeof(unsigned);
    int nblocks = (N + 127) / 128;
    mlp_score_kernel<<<nblocks, 256, smem_bytes>>>(x, W1, b1, W2, b2, N);

    // 2) segmented softmax + pooling (bounds found in-block)
    softmax_pool_kernel<<<G, 128>>>(x, batch, pooled, attn, N);
}

// round 5
// speedup vs baseline: 1.6126x; 1.0794x over previous
#include <cuda_runtime.h>
#include <cuda_bf16.h>

#define HDIM   128
#define HHALF  64

// -------- scratch (no device allocations allowed) --------
__device__ float g_s[1048576];             // per-row scores s[N]
__device__ float g_attn_fallback[1048576]; // only if out layout != pooled|attn

// ---------------------------------------------------------------------------
// helpers
// ---------------------------------------------------------------------------
static __device__ __forceinline__ float fast_tanh(float xv) {
    float ax = fabsf(xv);
    float t  = __expf(-2.0f * ax);
    float r  = __fdividef(1.0f - t, 1.0f + t);
    return copysignf(r, xv);
}

static __device__ __forceinline__ void split_bf16(float2 f, unsigned& hi, unsigned& lo) {
    __nv_bfloat162 h = __floats2bfloat162_rn(f.x, f.y);     // .x in low 16 bits
    float2 hf = __bfloat1622float2(h);
    __nv_bfloat162 l = __floats2bfloat162_rn(f.x - hf.x, f.y - hf.y);
    hi = *reinterpret_cast<unsigned*>(&h);
    lo = *reinterpret_cast<unsigned*>(&l);
}

static __device__ __forceinline__ void mma_bf16(float* c, const unsigned* a,
                                                unsigned b0, unsigned b1) {
    asm volatile(
        "mma.sync.aligned.m16n8k16.row.col.f32.bf16.bf16.f32 "
        "{%0,%1,%2,%3}, {%4,%5,%6,%7}, {%8,%9}, {%0,%1,%2,%3};\n"
        : "+f"(c[0]), "+f"(c[1]), "+f"(c[2]), "+f"(c[3])
        : "r"(a[0]), "r"(a[1]), "r"(a[2]), "r"(a[3]), "r"(b0), "r"(b1));
}

// ---------------------------------------------------------------------------
// Kernel 1: s = tanh(x @ W1 + b1) @ W2 + b2
// Tensor-core GEMM, bf16 hi/lo 3-pass split. B fragments packed as uint4 in
// smem -> ONE LDS.128 per j-step (feeds 3 MMAs), warp-contiguous 512B.
// ---------------------------------------------------------------------------
__global__ __launch_bounds__(256, 2)
void mlp_score_kernel(const float* __restrict__ x,
                      const float* __restrict__ W1,
                      const float* __restrict__ b1,
                      const float* __restrict__ W2,
                      const float* __restrict__ b2,
                      int n)
{
    // w1pack[ks][n][tig] = {bh0, bh1, bl0, bl1} for k0 = ks*16 + 2*tig
    __shared__ uint4  w1pack[8 * 64 * 4];      // 32 KB
    __shared__ float  b1s[HHALF];
    __shared__ float  w2s[HHALF];

    const int tid  = threadIdx.x;
    const int warp = tid >> 5;
    const int lane = tid & 31;
    const int g    = lane >> 2;     // groupID 0..7
    const int tig  = lane & 3;      // thread-in-group 0..3
    const int row0 = blockIdx.x * 128 + warp * 16;

    // ---- stage W1 as packed bf16 hi/lo fragments ----
    for (int i = tid; i < 8 * 64 * 4; i += 256) {
        int t  = i & 3;             // tig
        int nn = (i >> 2) & 63;     // col
        int ks = i >> 8;            // k16-step
        int k0 = ks * 16 + t * 2;
        float v0 = W1[(k0)     * HHALF + nn];
        float v1 = W1[(k0 + 1) * HHALF + nn];
        float v2 = W1[(k0 + 8) * HHALF + nn];
        float v3 = W1[(k0 + 9) * HHALF + nn];
        unsigned h0, l0, h1, l1;
        split_bf16(make_float2(v0, v1), h0, l0);
        split_bf16(make_float2(v2, v3), h1, l1);
        w1pack[i] = make_uint4(h0, h1, l0, l1);
    }
    if (tid < HHALF) { b1s[tid] = b1[tid]; w2s[tid] = W2[tid]; }
    __syncthreads();

    const int  rowA = row0 + g;
    const int  rowB = row0 + g + 8;
    const bool va   = rowA < n;
    const bool vb   = rowB < n;
    const float2* xa = (const float2*)x + (size_t)rowA * 64;
    const float2* xb = (const float2*)x + (size_t)rowB * 64;

    float C[8][4];
    #pragma unroll
    for (int j = 0; j < 8; j++)
        #pragma unroll
        for (int q = 0; q < 4; q++) C[j][q] = 0.f;

    const float2 z2 = make_float2(0.f, 0.f);

    #pragma unroll
    for (int kh = 0; kh < 2; kh++) {
        // load + split A fragments for 4 k16-steps
        unsigned ahi[4][4], alo[4][4];
        #pragma unroll
        for (int ks = 0; ks < 4; ks++) {
            int kp = (kh * 4 + ks) * 8 + tig;   // kpair index
            float2 f0 = va ? xa[kp]     : z2;
            float2 f1 = vb ? xb[kp]     : z2;
            float2 f2 = va ? xa[kp + 4] : z2;
            float2 f3 = vb ? xb[kp + 4] : z2;
            split_bf16(f0, ahi[ks][0], alo[ks][0]);
            split_bf16(f1, ahi[ks][1], alo[ks][1]);
            split_bf16(f2, ahi[ks][2], alo[ks][2]);
            split_bf16(f3, ahi[ks][3], alo[ks][3]);
        }
        // MMAs: one LDS.128 per (ks, j)
        #pragma unroll
        for (int ks = 0; ks < 4; ks++) {
            const int ksg = kh * 4 + ks;
            #pragma unroll
            for (int j = 0; j < 8; j++) {
                uint4 bf = w1pack[(ksg * 64 + j * 8 + g) * 4 + tig];
                mma_bf16(C[j], ahi[ks], bf.x, bf.y);   // hi*hi
                mma_bf16(C[j], alo[ks], bf.x, bf.y);   // lo*hi
                mma_bf16(C[j], ahi[ks], bf.z, bf.w);   // hi*lo
            }
        }
    }

    // ---- epilogue: tanh + dot(W2), reduce across tig lanes ----
    const float b2v = __ldg(b2);
    float p0 = 0.f, p1 = 0.f;
    #pragma unroll
    for (int j = 0; j < 8; j++) {
        int h0 = j * 8 + tig * 2, h1 = h0 + 1;
        float bb0 = b1s[h0], bb1 = b1s[h1];
        float ww0 = w2s[h0], ww1 = w2s[h1];
        p0 += fast_tanh(C[j][0] + bb0) * ww0 + fast_tanh(C[j][1] + bb1) * ww1;
        p1 += fast_tanh(C[j][2] + bb0) * ww0 + fast_tanh(C[j][3] + bb1) * ww1;
    }
    p0 += __shfl_xor_sync(0xffffffffu, p0, 1);
    p0 += __shfl_xor_sync(0xffffffffu, p0, 2);
    p1 += __shfl_xor_sync(0xffffffffu, p1, 1);
    p1 += __shfl_xor_sync(0xffffffffu, p1, 2);
    if (tig == 0) {
        if (va) g_s[rowA] = p0 + b2v;
        if (vb) g_s[rowB] = p1 + b2v;
    }
}

// ---------------------------------------------------------------------------
// Kernel 2: per-graph softmax + weighted pooling. ONE WARP PER GRAPH.
// No block barriers; shuffle reductions; exp cached in registers (len<=128);
// row weights broadcast via per-warp 32-float smem buffer; x rows loaded as
// one LDG.128 per lane, 4-row unroll.
// ---------------------------------------------------------------------------
__global__ __launch_bounds__(256)
void softmax_pool_kernel(const float* __restrict__ x,
                         const int*   __restrict__ batch,
                         float* __restrict__ pooled,
                         float* __restrict__ attn,
                         int n, int g_count)
{
    const int wid  = blockIdx.x * 8 + (threadIdx.x >> 5);
    const int lane = threadIdx.x & 31;
    if (wid >= g_count) return;

    __shared__ float wbuf_all[8][32];
    float* wbuf = wbuf_all[threadIdx.x >> 5];

    // segment bounds: lanes 0,1 binary-search lower_bound(batch, wid + lane)
    int pos = 0;
    if (lane < 2) {
        int target = wid + lane;
        int lo = 0, hi = n;
        while (lo < hi) {
            int mid = (lo + hi) >> 1;
            if (batch[mid] < target) lo = mid + 1; else hi = mid;
        }
        pos = lo;
    }
    const int start = __shfl_sync(0xffffffffu, pos, 0);
    const int end   = __shfl_sync(0xffffffffu, pos, 1);
    const int len   = end - start;

    float4* pout = (float4*)(pooled + (size_t)wid * HDIM) + lane;
    if (len <= 0) { *pout = make_float4(0.f, 0.f, 0.f, 0.f); return; }

    // --- max ---
    float mx = -3.402823466e38f;
    for (int i = lane; i < len; i += 32)
        mx = fmaxf(mx, g_s[start + i]);
    #pragma unroll
    for (int o = 16; o > 0; o >>= 1)
        mx = fmaxf(mx, __shfl_xor_sync(0xffffffffu, mx, o));

    // --- sum of exp; cache first 128 in registers ---
    float E[4];
    float sm = 0.f;
    #pragma unroll
    for (int r = 0; r < 4; r++) {
        int i = r * 32 + lane;
        float e = 0.f;
        if (i < len) { e = __expf(g_s[start + i] - mx); sm += e; }
        E[r] = e;
    }
    for (int i = 128 + lane; i < len; i += 32)
        sm += __expf(g_s[start + i] - mx);
    #pragma unroll
    for (int o = 16; o > 0; o >>= 1)
        sm += __shfl_xor_sync(0xffffffffu, sm, o);
    const float inv = 1.f / sm;

    // --- weighted pooling + attn writes ---
    float4 acc = make_float4(0.f, 0.f, 0.f, 0.f);
    const float4* xr = (const float4*)x + (size_t)start * 32 + lane;

    for (int c0 = 0; c0 < len; c0 += 32) {
        const int cl = min(32, len - c0);
        const int r  = c0 >> 5;
        // weights for this chunk of up to 32 rows
        float w;
        if (r < 4)       w = E[r] * inv;
        else             w = (lane < cl) ? __expf(g_s[start + c0 + lane] - mx) * inv : 0.f;
        if (lane < cl) {
            attn[start + c0 + lane] = w;
            wbuf[lane] = w;
        }
        __syncwarp();
        const float4* xc = xr + (size_t)c0 * 32;
        int j = 0;
        for (; j + 4 <= cl; j += 4) {
            float4 v0 = xc[(size_t)(j + 0) * 32];
            float4 v1 = xc[(size_t)(j + 1) * 32];
            float4 v2 = xc[(size_t)(j + 2) * 32];
            float4 v3 = xc[(size_t)(j + 3) * 32];
            float w0 = wbuf[j], w1 = wbuf[j + 1], w2 = wbuf[j + 2], w3 = wbuf[j + 3];
            acc.x = fmaf(v0.x, w0, acc.x); acc.y = fmaf(v0.y, w0, acc.y);
            acc.z = fmaf(v0.z, w0, acc.z); acc.w = fmaf(v0.w, w0, acc.w);
            acc.x = fmaf(v1.x, w1, acc.x); acc.y = fmaf(v1.y, w1, acc.y);
            acc.z = fmaf(v1.z, w1, acc.z); acc.w = fmaf(v1.w, w1, acc.w);
            acc.x = fmaf(v2.x, w2, acc.x); acc.y = fmaf(v2.y, w2, acc.y);
            acc.z = fmaf(v2.z, w2, acc.z); acc.w = fmaf(v2.w, w2, acc.w);
            acc.x = fmaf(v3.x, w3, acc.x); acc.y = fmaf(v3.y, w3, acc.y);
            acc.z = fmaf(v3.z, w3, acc.z); acc.w = fmaf(v3.w, w3, acc.w);
        }
        for (; j < cl; j++) {
            float4 v = xc[(size_t)j * 32];
            float wj = wbuf[j];
            acc.x = fmaf(v.x, wj, acc.x); acc.y = fmaf(v.y, wj, acc.y);
            acc.z = fmaf(v.z, wj, acc.z); acc.w = fmaf(v.w, wj, acc.w);
        }
        __syncwarp();
    }
    *pout = acc;
}

// ---------------------------------------------------------------------------
// launch
// ---------------------------------------------------------------------------
extern "C" void kernel_launch(void* const* d_in, const int* in_sizes, int n_in,
                              void* d_out, int out_size)
{
    const float* x     = (const float*)d_in[0];
    const int*   batch = (const int*)  d_in[1];
    const float* W1    = (const float*)d_in[2];
    const float* b1    = (const float*)d_in[3];
    const float* W2    = (const float*)d_in[4];
    const float* b2    = (const float*)d_in[5];

    const int N = in_sizes[1];
    float* out = (float*)d_out;

    // output layout: [x_pooled (G*128) | attn_weights (N)]
    long long rem = (long long)out_size - (long long)N;
    int G;
    float* pooled = out;
    float* attn;
    if (rem > 0 && (rem % HDIM) == 0) {
        G = (int)(rem / HDIM);
        attn = out + (size_t)G * HDIM;
    } else {
        G = out_size / HDIM;
        void* p = nullptr;
        cudaGetSymbolAddress(&p, g_attn_fallback);
        attn = (float*)p;
    }

    // 1) fused MLP scores (tensor cores)
    int nblocks = (N + 127) / 128;
    mlp_score_kernel<<<nblocks, 256>>>(x, W1, b1, W2, b2, N);

    // 2) segmented softmax + pooling (warp per graph)
    int pblocks = (G + 7) / 8;
    softmax_pool_kernel<<<pblocks, 256>>>(x, batch, pooled, attn, N, G);
}